// round 4
// baseline (speedup 1.0000x reference)
#include <cuda_runtime.h>
#include <cstdint>

#define NEGF  (-1e30f)
#define EPSF  (1e-7f)
#define LN2F  (0.6931471805599453f)
#define RPS   4            // time rows per ring slot
#define RING  4            // ring slots
#define NTDP  160          // DP threads (states)
#define NTHR  192          // total threads (160 DP + 32 producer)

__device__ __forceinline__ float ex2f_(float x) {
    float r; asm("ex2.approx.ftz.f32 %0, %1;" : "=f"(r) : "f"(x)); return r;
}
__device__ __forceinline__ float lg2f_(float x) {
    float r; asm("lg2.approx.ftz.f32 %0, %1;" : "=f"(r) : "f"(x)); return r;
}
__device__ __forceinline__ void barDP() {
    asm volatile("bar.sync 1, %0;" :: "r"(NTDP) : "memory");
}
__device__ __forceinline__ uint32_t s2u32(const void* p) {
    uint32_t a;
    asm("{ .reg .u64 t; cvta.to.shared.u64 t, %1; cvt.u32.u64 %0, t; }" : "=r"(a) : "l"(p));
    return a;
}
__device__ __forceinline__ void mbar_init(uint32_t m, uint32_t cnt) {
    asm volatile("mbarrier.init.shared.b64 [%0], %1;" :: "r"(m), "r"(cnt) : "memory");
}
__device__ __forceinline__ void mbar_expect_tx(uint32_t m, uint32_t bytes) {
    asm volatile("mbarrier.arrive.expect_tx.shared.b64 _, [%0], %1;" :: "r"(m), "r"(bytes) : "memory");
}
__device__ __forceinline__ void mbar_arrive(uint32_t m) {
    asm volatile("mbarrier.arrive.shared.b64 _, [%0];" :: "r"(m) : "memory");
}
__device__ __forceinline__ void mbar_wait_acq(uint32_t m, uint32_t parity) {
    asm volatile(
        "{\n\t.reg .pred P;\n"
        "W%=:\n\t"
        "mbarrier.try_wait.parity.acquire.cta.shared::cta.b64 P, [%0], %1, 0x989680;\n\t"
        "@P bra D%=;\n\t"
        "bra W%=;\n"
        "D%=:\n\t}"
        :: "r"(m), "r"(parity) : "memory");
}
__device__ __forceinline__ void mbar_wait_rlx(uint32_t m, uint32_t parity) {
    asm volatile(
        "{\n\t.reg .pred P;\n"
        "W%=:\n\t"
        "mbarrier.try_wait.parity.relaxed.cta.shared::cta.b64 P, [%0], %1, 0x989680;\n\t"
        "@P bra D%=;\n\t"
        "bra W%=;\n"
        "D%=:\n\t}"
        :: "r"(m), "r"(parity) : "memory");
}
__device__ __forceinline__ void bulk_copy(uint32_t dst_smem, const void* gsrc,
                                          uint32_t bytes, uint32_t mbar) {
    asm volatile(
        "cp.async.bulk.shared::cluster.global.mbarrier::complete_tx::bytes "
        "[%0], [%1], %2, [%3];"
        :: "r"(dst_smem), "l"(gsrc), "r"(bytes), "r"(mbar) : "memory");
}

// One CTA per batch row. A producer warp streams y_pred[b] row-blocks
// (RPS rows = contiguous 16KB) into a RING-slot shared ring with
// cp.async.bulk + mbarriers. 160 DP threads run the alpha recursion in
// log2 space, gathering emissions from the shared slot.
__global__ __launch_bounds__(NTHR)
void CTCLayer_5669356831169_kernel(const int* __restrict__ y_true,
                                   const float* __restrict__ y_pred,
                                   float* __restrict__ out,
                                   int T, int C, int L)
{
    extern __shared__ float sh[];
    const int b     = blockIdx.x;
    const int tid   = threadIdx.x;
    const int blank = C - 1;
    const int S     = 2 * L + 1;
    const int SLOT_F = RPS * C;                 // floats per slot
    const uint32_t SLOT_BYTES = SLOT_F * 4;

    // shared layout: ring[RING*SLOT_F] | mbar full[RING] empty[RING] (u64) |
    //                pad2 a0[NTDP] pad2 a1[NTDP] | ll
    float*    ring  = sh;
    uint64_t* mbars = (uint64_t*)(sh + RING * SLOT_F);
    float*    a0    = (float*)(mbars + 2 * RING) + 2;
    float*    a1    = a0 + NTDP + 2;
    int*      sh_ll = (int*)(a1 + NTDP);

    const uint32_t mb_base = s2u32(mbars);
    #define FULLB(s)  (mb_base + (uint32_t)(s) * 8u)
    #define EMPTYB(s) (mb_base + (uint32_t)(RING + (s)) * 8u)

    const int* yt = y_true + (size_t)b * L;

    if (tid == 0) {
        int ll = 0;
        for (int i = 0; i < L; ++i) ll += (yt[i] != -1);
        *sh_ll = ll;
        for (int i = 0; i < RING; ++i) { mbar_init(FULLB(i), 1); mbar_init(EMPTYB(i), 1); }
    }
    __syncthreads();

    const int NBLK = (T + RPS - 1) / RPS;

    if (tid >= NTDP) {
        // ---------------- producer warp (lane 0 does everything) ----------------
        if (tid == NTDP) {
            const char* gsrc = (const char*)(y_pred + (size_t)b * T * C);
            for (int blk = 0; blk < NBLK; ++blk) {
                int slot = blk & (RING - 1);
                if (blk >= RING)
                    mbar_wait_rlx(EMPTYB(slot), ((blk / RING) - 1) & 1);
                int rows = min(RPS, T - blk * RPS);
                uint32_t bytes = (uint32_t)rows * C * 4u;
                mbar_expect_tx(FULLB(slot), bytes);
                bulk_copy(s2u32(ring + slot * SLOT_F),
                          gsrc + (size_t)blk * SLOT_BYTES, bytes, FULLB(slot));
            }
        }
    } else {
        // ---------------- DP consumers ----------------
        const int s  = tid;
        const int ll = *sh_ll;

        int cls = blank;
        if ((s & 1) && s < S) {
            int raw = yt[(s - 1) >> 1];
            cls = (raw < 0) ? blank : raw;
        }
        const bool valid = (s < S) && (s < 2 * ll + 1);
        const bool has1  = (s >= 1);
        bool allow2 = false;
        if (s >= 2 && (s & 1) && s < S) {
            int r1 = yt[(s - 1) >> 1]; int c1 = (r1 < 0) ? blank : r1;
            int r2 = yt[(s - 3) >> 1]; int c2 = (r2 < 0) ? blank : r2;
            allow2 = (c1 != blank) && (c1 != c2);
        }

        float* rd = a0;
        float* wr = a1;
        float  my = NEGF;

        for (int blk = 0; blk < NBLK; ++blk) {
            int slot = blk & (RING - 1);
            mbar_wait_acq(FULLB(slot), (blk / RING) & 1);
            const float* sp = ring + slot * SLOT_F + cls;
            #pragma unroll
            for (int u = 0; u < RPS; ++u) {
                int t = blk * RPS + u;
                if (t < T) {
                    float p  = sp[u * C];
                    float le = lg2f_(p + EPSF);
                    float nv;
                    if (t == 0) {
                        nv = (valid && s < 2) ? le : NEGF;
                    } else {
                        float bb  = has1   ? rd[s - 1] : NEGF;
                        float cc2 = allow2 ? rd[s - 2] : NEGF;
                        float m0  = fmaxf(my, fmaxf(bb, cc2));
                        float sum = ex2f_(my - m0) + ex2f_(bb - m0) + ex2f_(cc2 - m0);
                        nv = valid ? (le + m0 + lg2f_(sum)) : NEGF;
                    }
                    wr[s] = nv;
                    my = nv;
                }
                barDP();
                if (t < T) { float* tmp = rd; rd = wr; wr = tmp; }
            }
            if (s == 0) mbar_arrive(EMPTYB(slot));
        }

        // rd holds alpha at t = T-1 (log2). loss = -ln2 * log2-addexp
        if (s == 0) {
            float x1 = rd[2 * ll];
            float x0 = (ll > 0) ? rd[2 * ll - 1] : NEGF;
            float m  = fmaxf(x1, x0);
            float r  = m + lg2f_(ex2f_(x1 - m) + ex2f_(x0 - m));
            out[b] = -LN2F * r;
        }
    }
    #undef FULLB
    #undef EMPTYB
}

extern "C" void kernel_launch(void* const* d_in, const int* in_sizes, int n_in,
                              void* d_out, int out_size) {
    const int*   y_true = (const int*)d_in[0];
    const float* y_pred = (const float*)d_in[1];
    float*       out    = (float*)d_out;

    const int B = out_size;                 // [B, 1]
    const int L = in_sizes[0] / B;          // 64
    const int C = 1024;
    const int T = in_sizes[1] / (B * C);    // 512

    const int SLOT_F = RPS * C;
    size_t smem = (size_t)RING * SLOT_F * sizeof(float)   // ring: 64 KB
                + 2 * RING * sizeof(uint64_t)             // mbarriers
                + (2 + NTDP + 2 + NTDP + 1) * sizeof(float);

    cudaFuncSetAttribute(CTCLayer_5669356831169_kernel,
                         cudaFuncAttributeMaxDynamicSharedMemorySize, (int)smem);

    CTCLayer_5669356831169_kernel<<<B, NTHR, smem>>>(y_true, y_pred, out, T, C, L);
}

// round 5
// speedup vs baseline: 1.2051x; 1.2051x over previous
#include <cuda_runtime.h>

#define NEGF  (-1e30f)
#define EPSF  (1e-7f)
#define LN2F  (0.6931471805599453f)
#define K_BLK 8          // time steps per producer/consumer block
#define RING  16         // ring slots (2 blocks)
#define NTDP  160        // DP threads: warps 0-2 even states, 3-4 odd states
#define NPROD 160        // producer threads
#define MAXQ  4          // gathers per producer thread per block
#define APAD  96         // padded alpha array length (dummy-lane safe)

__device__ __forceinline__ float ex2f_(float x) {
    float r; asm("ex2.approx.ftz.f32 %0, %1;" : "=f"(r) : "f"(x)); return r;
}
__device__ __forceinline__ float lg2f_(float x) {
    float r; asm("lg2.approx.ftz.f32 %0, %1;" : "=f"(r) : "f"(x)); return r;
}
__device__ __forceinline__ void barDP() {
    asm volatile("bar.sync 1, 160;" ::: "memory");
}

// One CTA per batch row. Producers (tid>=160) gather the <=L+1 unique class
// probs per time step from y_pred, compute log2(p+eps), stream into a shared
// ring (3-phase register pipeline). DP consumers: even extended states
// (blanks, 2-term LSE) on warps 0-2, odd states (labels, 3-term LSE) on
// warps 3-4; alpha ping-pongs through parity-split shared arrays with one
// named barrier per time step.
__global__ __launch_bounds__(320)
void CTCLayer_5669356831169_kernel(const int* __restrict__ y_true,
                                   const float* __restrict__ y_pred,
                                   float* __restrict__ out,
                                   int T, int C, int L)
{
    extern __shared__ float sh[];
    const int b     = blockIdx.x;
    const int tid   = threadIdx.x;
    const int blank = C - 1;
    const int ncls  = L + 1;          // 64 labels + blank (col ncls-1)
    const int slotw = ncls + 1;

    // layout: classes[ncls] | ring[RING*slotw] | AE0 AO0 AE1 AO1 [APAD each] | ll
    int*   classes = (int*)sh;
    float* ring    = sh + ncls;
    float* AE0     = ring + RING * slotw;
    float* AO0     = AE0 + APAD;
    float* AE1     = AO0 + APAD;
    float* AO1     = AE1 + APAD;
    int*   sh_ll   = (int*)(AO1 + APAD);

    const int* yt = y_true + (size_t)b * L;

    for (int j = tid; j < ncls; j += blockDim.x) {
        int c = blank;
        if (j < L) { int raw = yt[j]; c = (raw < 0) ? blank : raw; }
        classes[j] = c;
    }
    if (tid == 0) {
        int ll = 0;
        for (int i = 0; i < L; ++i) ll += (yt[i] != -1);
        *sh_ll = ll;
    }
    __syncthreads();
    const int ll = *sh_ll;

    const int NB  = (T + K_BLK - 1) / K_BLK;
    const int NB3 = ((NB + 2) / 3) * 3;

    if (tid >= NTDP) {
        // ------------------- producers -------------------
        const int pid = tid - NTDP;
        const float* yrow = y_pred + (size_t)b * T * C;
        const int LPB = K_BLK * ncls;

        int  uu[MAXQ], jj[MAXQ], cc[MAXQ];
        bool ok[MAXQ];
        #pragma unroll
        for (int i = 0; i < MAXQ; ++i) {
            int q = pid + NPROD * i;
            ok[i] = (q < LPB);
            int u = ok[i] ? q / ncls : 0;
            int j = ok[i] ? q % ncls : 0;
            uu[i] = u; jj[i] = j; cc[i] = classes[j];
        }

        float bv0[MAXQ], bv1[MAXQ], bv2[MAXQ];

        #define PLDG(buf, m) do {                                             \
            int _t0 = (m) * K_BLK;                                            \
            _Pragma("unroll")                                                 \
            for (int i = 0; i < MAXQ; ++i) {                                  \
                int _t = _t0 + uu[i];                                         \
                buf[i] = (ok[i] && _t < T)                                    \
                    ? __ldg(yrow + (size_t)_t * C + cc[i]) : 1.0f;            \
            } } while (0)

        #define PSTS(buf, m) do {                                             \
            int _t0 = (m) * K_BLK;                                            \
            _Pragma("unroll")                                                 \
            for (int i = 0; i < MAXQ; ++i) {                                  \
                int _t = _t0 + uu[i];                                         \
                if (ok[i] && _t < T)                                          \
                    ring[(_t % RING) * slotw + jj[i]] = lg2f_(buf[i] + EPSF); \
            } } while (0)

        PLDG(bv0, 0); PLDG(bv1, 1); PLDG(bv2, 2);
        PSTS(bv0, 0);
        __syncthreads();

        #define PITER(k, stsbuf, ldgbuf) do {                                 \
            int _m = (k) + 1;                                                 \
            if (_m < NB) PSTS(stsbuf, _m);                                    \
            int _ml = (k) + 3;                                                \
            if (_ml < NB) PLDG(ldgbuf, _ml);                                  \
            __syncthreads(); } while (0)

        for (int k = 0; k < NB3; k += 3) {
            PITER(k,     bv1, bv0);
            PITER(k + 1, bv2, bv1);
            PITER(k + 2, bv0, bv2);
        }
        #undef PITER
        #undef PSTS
        #undef PLDG
    } else if (tid < 96) {
        // ------------- even states: s = 2i (blank emissions, 2-term LSE) -------------
        const int  i     = tid;              // active for i <= 64; 65..95 dummy
        const bool act   = (i <= 64);
        const bool valid = act && (i <= ll); // s=2i within band: 2i < 2ll+1
        const int  bcol  = ncls - 1;

        float* ae_rd = AE0; float* ao_rd = AO0;
        float* ae_wr = AE1; float* ao_wr = AO1;
        float  my = NEGF;

        __syncthreads();   // matches producer prologue sync

        for (int k = 0; k < NB3; ++k) {
            int base = (k * K_BLK) % RING;
            float lea[K_BLK];
            #pragma unroll
            for (int u = 0; u < K_BLK; ++u)
                lea[u] = ring[(base + u) * slotw + bcol];
            #pragma unroll
            for (int u = 0; u < K_BLK; ++u) {
                int t = k * K_BLK + u;
                if (t < T) {
                    float nv;
                    if (t == 0) {
                        nv = (i == 0) ? lea[u] : NEGF;
                    } else {
                        float bb  = (i >= 1) ? ao_rd[i - 1] : NEGF;
                        float m0  = fmaxf(my, bb);
                        float lo  = fminf(my, bb);
                        float sum = 1.0f + ex2f_(lo - m0);
                        nv = valid ? (lea[u] + m0 + lg2f_(sum)) : NEGF;
                    }
                    if (act) ae_wr[i] = nv;
                    my = nv;
                }
                barDP();
                if (t < T) {
                    float* t0 = ae_rd; ae_rd = ae_wr; ae_wr = t0;
                    float* t1 = ao_rd; ao_rd = ao_wr; ao_wr = t1;
                }
            }
            __syncthreads();
        }

        if (tid == 0) {
            float x1 = ae_rd[ll];                              // alpha[2ll]
            float x0 = (ll > 0) ? ao_rd[ll - 1] : NEGF;        // alpha[2ll-1]
            float m  = fmaxf(x1, x0);
            float r  = m + lg2f_(ex2f_(x1 - m) + ex2f_(x0 - m));
            out[b] = -LN2F * r;
        }
    } else {
        // ------------- odd states: s = 2i+1 (label emissions, 3-term LSE) -------------
        const int  i     = tid - 96;         // 0..63, all active
        const bool valid = (i < ll);         // s=2i+1 < 2ll+1
        bool allow2 = false;
        if (i >= 1) {
            int c1 = classes[i], c2 = classes[i - 1];
            allow2 = (c1 != blank) && (c1 != c2);
        }

        float* ae_rd = AE0; float* ao_rd = AO0;
        float* ae_wr = AE1; float* ao_wr = AO1;
        float  my = NEGF;

        __syncthreads();   // matches producer prologue sync

        for (int k = 0; k < NB3; ++k) {
            int base = (k * K_BLK) % RING;
            float lea[K_BLK];
            #pragma unroll
            for (int u = 0; u < K_BLK; ++u)
                lea[u] = ring[(base + u) * slotw + i];
            #pragma unroll
            for (int u = 0; u < K_BLK; ++u) {
                int t = k * K_BLK + u;
                if (t < T) {
                    float nv;
                    if (t == 0) {
                        nv = (i == 0 && valid) ? lea[u] : NEGF;
                    } else {
                        float bb = ae_rd[i];                       // s-1 = 2i
                        float cc = allow2 ? ao_rd[i - 1] : NEGF;   // s-2 = 2i-1
                        // branch-free {hi, mid, lo} of {my, bb, cc} (no cancellation)
                        float x  = fmaxf(my, bb);
                        float n  = fminf(my, bb);
                        float hi = fmaxf(x, cc);
                        float lo = fminf(n, cc);
                        float mid = fmaxf(n, fminf(x, cc));
                        float sum = 1.0f + ex2f_(lo - hi) + ex2f_(mid - hi);
                        nv = valid ? (lea[u] + hi + lg2f_(sum)) : NEGF;
                    }
                    ao_wr[i] = nv;
                    my = nv;
                }
                barDP();
                if (t < T) {
                    float* t0 = ae_rd; ae_rd = ae_wr; ae_wr = t0;
                    float* t1 = ao_rd; ao_rd = ao_wr; ao_wr = t1;
                }
            }
            __syncthreads();
        }
    }
}

extern "C" void kernel_launch(void* const* d_in, const int* in_sizes, int n_in,
                              void* d_out, int out_size) {
    const int*   y_true = (const int*)d_in[0];
    const float* y_pred = (const float*)d_in[1];
    float*       out    = (float*)d_out;

    const int B = out_size;                 // [B, 1]
    const int L = in_sizes[0] / B;          // 64
    const int C = 1024;
    const int T = in_sizes[1] / (B * C);    // 512

    const int ncls  = L + 1;
    const int slotw = ncls + 1;
    size_t smem = (size_t)(ncls + RING * slotw + 4 * APAD + 1) * sizeof(float);

    CTCLayer_5669356831169_kernel<<<B, NTDP + NPROD, smem>>>(y_true, y_pred, out, T, C, L);
}

// round 6
// speedup vs baseline: 1.3425x; 1.1140x over previous
#include <cuda_runtime.h>
#include <cstdint>

#define NEGF   (-1e30f)
#define EPSF   (1e-7f)
#define LN2F   (0.6931471805599453f)
#define KB     8            // time steps per ring block
#define RINGT  16           // ring time-slots (2 blocks)
#define NRB    2            // ring blocks
#define NTDP   32           // DP warp
#define NPROD  160          // producer threads
#define NTHR   192
#define NS     5            // states per DP lane (32*5 = 160 >= 129)
#define NCLS   65           // L labels + blank
#define SLOTW  66
#define MAXQ   4

__device__ __forceinline__ float ex2f_(float x) {
    float r; asm("ex2.approx.ftz.f32 %0, %1;" : "=f"(r) : "f"(x)); return r;
}
__device__ __forceinline__ float lg2f_(float x) {
    float r; asm("lg2.approx.ftz.f32 %0, %1;" : "=f"(r) : "f"(x)); return r;
}
__device__ __forceinline__ uint32_t s2u32(const void* p) {
    uint32_t a;
    asm("{ .reg .u64 t; cvta.to.shared.u64 t, %1; cvt.u32.u64 %0, t; }" : "=r"(a) : "l"(p));
    return a;
}
__device__ __forceinline__ void mbar_init(uint32_t m, uint32_t cnt) {
    asm volatile("mbarrier.init.shared.b64 [%0], %1;" :: "r"(m), "r"(cnt) : "memory");
}
__device__ __forceinline__ void mbar_arrive(uint32_t m) {
    asm volatile("mbarrier.arrive.shared.b64 _, [%0];" :: "r"(m) : "memory");
}
__device__ __forceinline__ void mbar_wait_acq(uint32_t m, uint32_t parity) {
    asm volatile(
        "{\n\t.reg .pred P;\n"
        "W%=:\n\t"
        "mbarrier.try_wait.parity.acquire.cta.shared::cta.b64 P, [%0], %1, 0x989680;\n\t"
        "@P bra D%=;\n\t"
        "bra W%=;\n"
        "D%=:\n\t}"
        :: "r"(m), "r"(parity) : "memory");
}

// One CTA per batch row. 160 producer threads gather the 65 unique class
// probs per time step (streaming loads), compute log2(p+eps), and fill a
// 16-slot shared ring, 3 blocks ahead. The DP runs on ONE warp: lane l holds
// states [5l, 5l+5) in registers; cross-lane alpha[s-1], alpha[s-2] come from
// two __shfl_up per step. No __syncthreads / bar.sync on the recurrence;
// producer<->consumer handoff is full/empty mbarriers once per 8 steps.
__global__ __launch_bounds__(NTHR)
void CTCLayer_5669356831169_kernel(const int* __restrict__ y_true,
                                   const float* __restrict__ y_pred,
                                   float* __restrict__ out,
                                   int T, int C, int L)
{
    __shared__ int   classes[NCLS];
    __shared__ float ring[RINGT * SLOTW];
    __shared__ float afinal[NTDP * NS];
    __shared__ __align__(8) unsigned long long mbars[2 * NRB]; // full[0..1], empty[2..3]
    __shared__ int sh_ll;

    const int b     = blockIdx.x;
    const int tid   = threadIdx.x;
    const int blank = C - 1;
    const int S     = 2 * L + 1;

    const uint32_t mb = s2u32(mbars);
    #define FULLB(r)  (mb + (uint32_t)(r) * 8u)
    #define EMPTYB(r) (mb + (uint32_t)(NRB + (r)) * 8u)

    const int* yt = y_true + (size_t)b * L;

    for (int j = tid; j < NCLS; j += NTHR) {
        int c = blank;
        if (j < L) { int raw = yt[j]; c = (raw < 0) ? blank : raw; }
        classes[j] = c;
    }
    if (tid == 0) {
        int ll = 0;
        for (int i = 0; i < L; ++i) ll += (yt[i] != -1);
        sh_ll = ll;
        for (int r = 0; r < NRB; ++r) {
            mbar_init(FULLB(r), NPROD);
            mbar_init(EMPTYB(r), 1);
        }
    }
    __syncthreads();
    const int ll = sh_ll;

    const int NB  = (T + KB - 1) / KB;          // 64
    const int NB3 = ((NB + 2) / 3) * 3;         // 66

    if (tid >= NTDP) {
        // ------------------------ producers ------------------------
        const int pid = tid - NTDP;
        const float* yrow = y_pred + (size_t)b * T * C;
        const int LPB = KB * NCLS;              // 520 gathers per block

        int  uu[MAXQ], jj[MAXQ], cc[MAXQ];
        bool ok[MAXQ];
        #pragma unroll
        for (int i = 0; i < MAXQ; ++i) {
            int q = pid + NPROD * i;
            ok[i] = (q < LPB);
            int u = ok[i] ? q / NCLS : 0;
            int j = ok[i] ? q % NCLS : 0;
            uu[i] = u; jj[i] = j; cc[i] = classes[j];
        }

        float bv0[MAXQ], bv1[MAXQ], bv2[MAXQ];

        #define PLDG(buf, m) do {                                             \
            int _t0 = (m) * KB;                                               \
            _Pragma("unroll")                                                 \
            for (int i = 0; i < MAXQ; ++i) {                                  \
                int _t = _t0 + uu[i];                                         \
                buf[i] = (ok[i] && _t < T)                                    \
                    ? __ldcs(yrow + (size_t)_t * C + cc[i]) : 1.0f;           \
            } } while (0)

        #define PSTS(buf, m) do {                                             \
            int _t0 = (m) * KB;                                               \
            _Pragma("unroll")                                                 \
            for (int i = 0; i < MAXQ; ++i) {                                  \
                int _t = _t0 + uu[i];                                         \
                if (ok[i] && _t < T)                                          \
                    ring[(_t & (RINGT - 1)) * SLOTW + jj[i]]                  \
                        = lg2f_(buf[i] + EPSF);                               \
            } } while (0)

        #define PBLK(m, buf) do {                                             \
            if ((m) < NB) {                                                   \
                if ((m) >= NRB)                                               \
                    mbar_wait_acq(EMPTYB((m) & 1), (((m) >> 1) - 1) & 1);     \
                PSTS(buf, m);                                                 \
                mbar_arrive(FULLB((m) & 1));                                  \
            } } while (0)

        PLDG(bv0, 0); PLDG(bv1, 1); PLDG(bv2, 2);

        for (int k = 0; k < NB3; k += 3) {
            PBLK(k,     bv0);  PLDG(bv0, k + 3);
            PBLK(k + 1, bv1);  PLDG(bv1, k + 4);
            PBLK(k + 2, bv2);  PLDG(bv2, k + 5);
        }
        #undef PBLK
        #undef PSTS
        #undef PLDG
    } else {
        // ------------------------ DP warp ------------------------
        const int l = tid;                       // lane 0..31
        int  col[NS];
        bool allow2[NS], validb[NS], lead[NS];
        #pragma unroll
        for (int j = 0; j < NS; ++j) {
            int s = NS * l + j;
            bool sv = (s < S) && (s < 2 * ll + 1);
            validb[j] = sv;
            lead[j]   = sv && (s < 2);
            allow2[j] = false;
            col[j]    = NCLS - 1;                // blank column default
            if ((s & 1) && s < S) {
                int i = (s - 1) >> 1;            // 0..63
                col[j] = i;
                if (i >= 1) {
                    int c1 = classes[i], c2 = classes[i - 1];
                    allow2[j] = (c1 != blank) && (c1 != c2);
                }
            }
        }

        float a[NS];
        #pragma unroll
        for (int j = 0; j < NS; ++j) a[j] = NEGF;

        for (int k = 0; k < NB; ++k) {
            int rb = k & 1;
            mbar_wait_acq(FULLB(rb), (k >> 1) & 1);

            #pragma unroll
            for (int u = 0; u < KB; ++u) {
                int t = k * KB + u;
                const float* rp = ring + (size_t)((t & (RINGT - 1)) * SLOTW);
                float le[NS];
                #pragma unroll
                for (int j = 0; j < NS; ++j) le[j] = rp[col[j]];

                float up1 = __shfl_up_sync(0xffffffffu, a[NS - 1], 1);
                float up2 = __shfl_up_sync(0xffffffffu, a[NS - 2], 1);
                if (l == 0) { up1 = NEGF; up2 = NEGF; }

                float na[NS];
                #pragma unroll
                for (int j = 0; j < NS; ++j) {
                    float bb = (j >= 1) ? a[j - 1] : up1;
                    float cc = (j >= 2) ? a[j - 2] : ((j == 1) ? up1 : up2);
                    cc = allow2[j] ? cc : NEGF;
                    float x   = fmaxf(a[j], bb);
                    float n   = fminf(a[j], bb);
                    float hi  = fmaxf(x, cc);
                    float lo  = fminf(n, cc);
                    float mid = fmaxf(n, fminf(x, cc));
                    float sum = 1.0f + ex2f_(lo - hi) + ex2f_(mid - hi);
                    na[j] = validb[j] ? (le[j] + hi + lg2f_(sum)) : NEGF;
                }
                if (t == 0) {
                    #pragma unroll
                    for (int j = 0; j < NS; ++j)
                        na[j] = lead[j] ? le[j] : NEGF;
                }
                #pragma unroll
                for (int j = 0; j < NS; ++j) a[j] = na[j];
            }
            __syncwarp();
            if (l == 0) mbar_arrive(EMPTYB(rb));
        }

        #pragma unroll
        for (int j = 0; j < NS; ++j) afinal[NS * l + j] = a[j];
        __syncwarp();
        if (l == 0) {
            float x1 = afinal[2 * ll];
            float x0 = (ll > 0) ? afinal[2 * ll - 1] : NEGF;
            float m  = fmaxf(x1, x0);
            float r  = m + lg2f_(ex2f_(x1 - m) + ex2f_(x0 - m));
            out[b] = -LN2F * r;
        }
    }
    #undef FULLB
    #undef EMPTYB
}

extern "C" void kernel_launch(void* const* d_in, const int* in_sizes, int n_in,
                              void* d_out, int out_size) {
    const int*   y_true = (const int*)d_in[0];
    const float* y_pred = (const float*)d_in[1];
    float*       out    = (float*)d_out;

    const int B = out_size;                 // [B, 1]
    const int L = in_sizes[0] / B;          // 64  (NCLS = L+1 = 65)
    const int C = 1024;
    const int T = in_sizes[1] / (B * C);    // 512

    CTCLayer_5669356831169_kernel<<<B, NTHR>>>(y_true, y_pred, out, T, C, L);
}